// round 7
// baseline (speedup 1.0000x reference)
#include <cuda_runtime.h>
#include <math.h>

// Problem constants
#define BB 16
#define CF 96
#define HH 128
#define WW 128
#define HW (HH*WW)

// Scratch (static device allocations are allowed)
__device__ float g_flow[BB*2*HW];        //   2 MB
__device__ float g_feat2[BB*CF*HW];      //  96 MB
__device__ float g_corr[BB*49*HW];       //  49 MB
__device__ float g_x1[BB*128*HW];        // 128 MB
__device__ float g_x2[BB*64*HW];         //  64 MB
__device__ float g_x3[BB*32*HW];         //  32 MB

// Packed f32x2 FMA (FFMA2 in SASS; PTX-only form)
#define FMA2(d,a,b,c) asm("fma.rn.f32x2 %0, %1, %2, %3;" : "=l"(d) : "l"(a), "l"(b), "l"(c))

__device__ __forceinline__ unsigned long long pack2(float lo, float hi) {
    unsigned long long r;
    asm("mov.b64 %0, {%1, %2};" : "=l"(r) : "f"(lo), "f"(hi));
    return r;
}

// ---------------------------------------------------------------------------
// 1) upflow: transposed conv, stride 2, 4x4 kernel, groups=2
// ---------------------------------------------------------------------------
__global__ void k_upflow(const float* __restrict__ flow, const float* __restrict__ wu)
{
    int idx = blockIdx.x * blockDim.x + threadIdx.x;
    if (idx >= BB*2*HW) return;
    int ox = idx & 127;
    int oy = (idx >> 7) & 127;
    int c  = (idx >> 14) & 1;
    int b  = idx >> 15;
    const float* f  = flow + (b*2 + c) * 64 * 64;
    const float* wc = wu + c * 16;
    int py = oy & 1, px = ox & 1;
    float s = 0.f;
#pragma unroll
    for (int i = 0; i < 2; i++) {
        int ky  = py + 2*i;
        int jy2 = oy + ky - 2;
        if (jy2 < 0 || jy2 > 126) continue;
        int jy = jy2 >> 1;
#pragma unroll
        for (int j = 0; j < 2; j++) {
            int kx  = px + 2*j;
            int jx2 = ox + kx - 2;
            if (jx2 < 0 || jx2 > 126) continue;
            int jx = jx2 >> 1;
            s += f[jy*64 + jx] * wc[(3-ky)*4 + (3-kx)];
        }
    }
    g_flow[idx] = s;
}

// ---------------------------------------------------------------------------
// 2) backward warp of featSecond by 2.5*flow, bilinear zero-border + mask
// ---------------------------------------------------------------------------
__global__ void k_warp(const float* __restrict__ feat)
{
    int idx = blockIdx.x * blockDim.x + threadIdx.x;
    if (idx >= BB*HW) return;
    int x = idx & 127;
    int y = (idx >> 7) & 127;
    int b = idx >> 14;

    float fx = (float)x + 2.5f * g_flow[(b*2 + 0)*HW + y*WW + x];
    float fy = (float)y + 2.5f * g_flow[(b*2 + 1)*HW + y*WW + x];

    float x0f = floorf(fx), y0f = floorf(fy);
    float x1f = x0f + 1.f,  y1f = y0f + 1.f;
    float wa = (x1f - fx) * (y1f - fy);
    float wb = (fx - x0f) * (y1f - fy);
    float wc = (x1f - fx) * (fy - y0f);
    float wd = (fx - x0f) * (fy - y0f);

    int x0 = (int)x0f, y0 = (int)y0f, x1 = x0 + 1, y1 = y0 + 1;
    float vx0 = (x0 >= 0 && x0 < WW) ? 1.f : 0.f;
    float vx1 = (x1 >= 0 && x1 < WW) ? 1.f : 0.f;
    float vy0 = (y0 >= 0 && y0 < HH) ? 1.f : 0.f;
    float vy1 = (y1 >= 0 && y1 < HH) ? 1.f : 0.f;
    float va = vx0*vy0, vb = vx1*vy0, vc = vx0*vy1, vd = vx1*vy1;

    float onew = wa*va + wb*vb + wc*vc + wd*vd;
    float mask = (onew > 0.999f) ? 1.f : 0.f;

    float ka = wa*va*mask, kb = wb*vb*mask, kc = wc*vc*mask, kd = wd*vd*mask;

    int cx0 = min(max(x0, 0), WW-1), cx1 = min(max(x1, 0), WW-1);
    int cy0 = min(max(y0, 0), HH-1), cy1 = min(max(y1, 0), HH-1);
    int ia = cy0*WW + cx0, ib2 = cy0*WW + cx1, ic2 = cy1*WW + cx0, id2 = cy1*WW + cx1;

    const float* base = feat + (size_t)b*CF*HW;
    float* out = g_feat2 + (size_t)b*CF*HW + y*WW + x;
#pragma unroll 4
    for (int c = 0; c < CF; c++) {
        const float* p = base + c*HW;
        out[c*HW] = ka*__ldg(p+ia) + kb*__ldg(p+ib2) + kc*__ldg(p+ic2) + kd*__ldg(p+id2);
    }
}

// ---------------------------------------------------------------------------
// 3) correlation (7x7 displacements, mean over 96 channels) + leaky relu
// ---------------------------------------------------------------------------
__global__ __launch_bounds__(256) void k_corr(const float* __restrict__ f1)
{
    __shared__ float s2[22*22];
    int tx = threadIdx.x, ty = threadIdx.y;
    int tid = ty*16 + tx;
    int bx0 = blockIdx.x * 16, by0 = blockIdx.y * 16;
    int b = blockIdx.z;
    int x = bx0 + tx, y = by0 + ty;
    int ox0 = bx0 - 3, oy0 = by0 - 3;

    float acc[49];
#pragma unroll
    for (int d = 0; d < 49; d++) acc[d] = 0.f;

    const float* F1 = f1 + (size_t)b*CF*HW;
    const float* F2 = g_feat2 + (size_t)b*CF*HW;

    for (int c = 0; c < CF; c++) {
        __syncthreads();
#pragma unroll
        for (int i = tid; i < 22*22; i += 256) {
            int ly = i / 22, lx = i - ly*22;
            int gy = oy0 + ly, gx = ox0 + lx;
            float v = 0.f;
            if (gy >= 0 && gy < HH && gx >= 0 && gx < WW)
                v = F2[c*HW + gy*WW + gx];
            s2[i] = v;
        }
        float a1 = F1[c*HW + y*WW + x];
        __syncthreads();
#pragma unroll
        for (int dy = 0; dy < 7; dy++)
#pragma unroll
            for (int dx = 0; dx < 7; dx++)
                acc[dy*7 + dx] += a1 * s2[(ty+dy)*22 + tx + dx];
    }

    const float inv = 1.f / 96.f;
    float* out = g_corr + (size_t)b*49*HW + y*WW + x;
#pragma unroll
    for (int d = 0; d < 49; d++) {
        float v = acc[d] * inv;
        out[d*HW] = (v >= 0.f) ? v : 0.1f * v;
    }
}

// ---------------------------------------------------------------------------
// 4) 3x3 conv, pad 1, f32x2-packed, each thread: 2(x) x 4(y) pixels, OCT ocs.
//    Block 16x16 -> spatial tile 32(w) x 64(h). Grid.x = 4*2 = 8 tiles.
// ---------------------------------------------------------------------------
template <int IC, int OC, int OCT>
__global__ __launch_bounds__(256, 2) void k_conv3f2(const float* __restrict__ in,
                                                    const float* __restrict__ w,
                                                    const float* __restrict__ bias,
                                                    float* __restrict__ out)
{
    __shared__ float s_in[66*34];
    __shared__ float s_w2[OCT*9*2];   // duplicated (w,w) pairs for LDS.64 broadcast
    int tx = threadIdx.x, ty = threadIdx.y;
    int tid = ty*16 + tx;
    int tile = blockIdx.x;            // 0..7 : 4 x-tiles * 2 y-tiles
    int tbx = (tile & 3) * 32;
    int tby = (tile >> 2) * 64;
    int ocb = blockIdx.y * OCT;
    int b = blockIdx.z;

    unsigned long long acc[OCT][4];
#pragma unroll
    for (int o = 0; o < OCT; o++) {
        float bb = bias[ocb + o];
        unsigned long long bp = pack2(bb, bb);
#pragma unroll
        for (int py = 0; py < 4; py++) acc[o][py] = bp;
    }

    const float* IN = in + (size_t)b*IC*HW;

    for (int ic = 0; ic < IC; ic++) {
        __syncthreads();
        const float* src = IN + ic*HW;
        // stage 66x34 input tile (1-halo, zero pad)
#pragma unroll
        for (int i = tid; i < 66*34; i += 256) {
            int ly = i / 34, lx = i - ly*34;
            int gy = tby - 1 + ly, gx = tbx - 1 + lx;
            float v = 0.f;
            if (gy >= 0 && gy < HH && gx >= 0 && gx < WW)
                v = __ldg(src + gy*WW + gx);
            s_in[i] = v;
        }
        if (tid < OCT*9) {
            int o = tid / 9, t = tid - o*9;
            float wv = w[((size_t)(ocb + o)*IC + ic)*9 + t];
            s_w2[tid*2]   = wv;
            s_w2[tid*2+1] = wv;
        }
        __syncthreads();

#pragma unroll
        for (int r = 0; r < 3; r++) {
            unsigned long long p0[4], p1[4], p2[4];
#pragma unroll
            for (int py = 0; py < 4; py++) {
                const float* rp = &s_in[(ty*4 + r + py)*34 + 2*tx];
                p0[py] = *(const unsigned long long*)(rp);       // cols (s=0, s=0+1)
                p2[py] = *(const unsigned long long*)(rp + 2);   // cols (s=2, s=2+1)
                unsigned int mlo = (unsigned int)(p0[py] >> 32);
                unsigned int mhi = (unsigned int)(p2[py]);
                p1[py] = ((unsigned long long)mhi << 32) | mlo;  // cols (s=1, s=1+1)
            }
#pragma unroll
            for (int o = 0; o < OCT; o++) {
                unsigned long long w0 = *(const unsigned long long*)&s_w2[(o*9 + r*3 + 0)*2];
                unsigned long long w1 = *(const unsigned long long*)&s_w2[(o*9 + r*3 + 1)*2];
                unsigned long long w2v= *(const unsigned long long*)&s_w2[(o*9 + r*3 + 2)*2];
#pragma unroll
                for (int py = 0; py < 4; py++) {
                    FMA2(acc[o][py], p0[py], w0,  acc[o][py]);
                    FMA2(acc[o][py], p1[py], w1,  acc[o][py]);
                    FMA2(acc[o][py], p2[py], w2v, acc[o][py]);
                }
            }
        }
    }

    int x0 = tbx + 2*tx;
#pragma unroll
    for (int o = 0; o < OCT; o++) {
#pragma unroll
        for (int py = 0; py < 4; py++) {
            int y = tby + ty*4 + py;
            float a0 = __uint_as_float((unsigned int)(acc[o][py] & 0xFFFFFFFFull));
            float a1 = __uint_as_float((unsigned int)(acc[o][py] >> 32));
            a0 = (a0 >= 0.f) ? a0 : 0.1f*a0;
            a1 = (a1 >= 0.f) ? a1 : 0.1f*a1;
            *(float2*)&out[((size_t)b*OC + ocb + o)*HW + y*WW + x0] = make_float2(a0, a1);
        }
    }
}

// ---------------------------------------------------------------------------
// 5) final 5x5 conv (32 -> 2, pad 2), add upsampled flow, write d_out
// ---------------------------------------------------------------------------
__global__ __launch_bounds__(256) void k_conv5(const float* __restrict__ w,
                                               const float* __restrict__ bias,
                                               float* __restrict__ out)
{
    __shared__ float s_in[20*20];
    __shared__ float s_w[2*25];
    int tx = threadIdx.x, ty = threadIdx.y;
    int tid = ty*16 + tx;
    int tile = blockIdx.x;
    int tbx = (tile & 7) * 16, tby = (tile >> 3) * 16;
    int b = blockIdx.z;
    int x = tbx + tx, y = tby + ty;

    float acc0 = bias[0], acc1 = bias[1];
    const float* IN = g_x3 + (size_t)b*32*HW;

    for (int ic = 0; ic < 32; ic++) {
        __syncthreads();
#pragma unroll
        for (int i = tid; i < 400; i += 256) {
            int ly = i / 20, lx = i - ly*20;
            int gy = tby - 2 + ly, gx = tbx - 2 + lx;
            float v = 0.f;
            if (gy >= 0 && gy < HH && gx >= 0 && gx < WW)
                v = IN[ic*HW + gy*WW + gx];
            s_in[i] = v;
        }
        if (tid < 50) {
            int o = tid / 25, t = tid - o*25;
            s_w[tid] = w[((size_t)o*32 + ic)*25 + t];
        }
        __syncthreads();

#pragma unroll
        for (int t = 0; t < 25; t++) {
            int r = t / 5, s = t - r*5;
            float iv = s_in[(ty + r)*20 + tx + s];
            acc0 += iv * s_w[t];
            acc1 += iv * s_w[25 + t];
        }
    }

    int pix = y*WW + x;
    out[((size_t)b*2 + 0)*HW + pix] = g_flow[(b*2 + 0)*HW + pix] + acc0;
    out[((size_t)b*2 + 1)*HW + pix] = g_flow[(b*2 + 1)*HW + pix] + acc1;
}

// ---------------------------------------------------------------------------
extern "C" void kernel_launch(void* const* d_in, const int* in_sizes, int n_in,
                              void* d_out, int out_size)
{
    const float* featFirst  = (const float*)d_in[2];
    const float* featSecond = (const float*)d_in[3];
    const float* tflow      = (const float*)d_in[4];
    const float* wu         = (const float*)d_in[5];
    const float* w1 = (const float*)d_in[6];
    const float* b1 = (const float*)d_in[7];
    const float* w2 = (const float*)d_in[8];
    const float* b2 = (const float*)d_in[9];
    const float* w3 = (const float*)d_in[10];
    const float* b3 = (const float*)d_in[11];
    const float* w4 = (const float*)d_in[12];
    const float* b4 = (const float*)d_in[13];

    float *corrp, *x1p, *x2p, *x3p;
    cudaGetSymbolAddress((void**)&corrp, g_corr);
    cudaGetSymbolAddress((void**)&x1p, g_x1);
    cudaGetSymbolAddress((void**)&x2p, g_x2);
    cudaGetSymbolAddress((void**)&x3p, g_x3);

    dim3 blk(16, 16);

    k_upflow<<<(BB*2*HW + 255)/256, 256>>>(tflow, wu);
    k_warp<<<(BB*HW + 255)/256, 256>>>(featSecond);
    k_corr<<<dim3(8, 8, BB), blk>>>(featFirst);
    k_conv3f2<49, 128, 8><<<dim3(8, 16, BB), blk>>>(corrp, w1, b1, x1p);
    k_conv3f2<128, 64, 8><<<dim3(8,  8, BB), blk>>>(x1p,  w2, b2, x2p);
    k_conv3f2<64,  32, 8><<<dim3(8,  4, BB), blk>>>(x2p,  w3, b3, x3p);
    k_conv5<<<dim3(64, 1, BB), blk>>>(w4, b4, (float*)d_out);
}

// round 9
// speedup vs baseline: 1.4784x; 1.4784x over previous
#include <cuda_runtime.h>
#include <math.h>
#include <stdint.h>

// Problem constants
#define BB 16
#define CF 96
#define HH 128
#define WW 128
#define HW (HH*WW)

// Scratch (static device allocations are allowed)
__device__ float g_flow[BB*2*HW];        //   2 MB
__device__ float g_feat2[BB*CF*HW];      //  96 MB
__device__ float g_corr[BB*49*HW];       //  49 MB
__device__ float g_x1[BB*128*HW];        // 128 MB
__device__ float g_x2[BB*64*HW];         //  64 MB
__device__ float g_x3[BB*32*HW];         //  32 MB

// Packed f32x2 FMA (FFMA2 in SASS; PTX-only form)
#define FMA2(d,a,b,c) asm("fma.rn.f32x2 %0, %1, %2, %3;" : "=l"(d) : "l"(a), "l"(b), "l"(c))

__device__ __forceinline__ unsigned long long pack2(float lo, float hi) {
    unsigned long long r;
    asm("mov.b64 %0, {%1, %2};" : "=l"(r) : "f"(lo), "f"(hi));
    return r;
}

__device__ __forceinline__ uint32_t smem_u32(const void* p) {
    return (uint32_t)__cvta_generic_to_shared(p);
}
__device__ __forceinline__ void cp4(uint32_t dst, const void* src) {
    asm volatile("cp.async.ca.shared.global [%0], [%1], 4;" :: "r"(dst), "l"(src));
}
#define CP_COMMIT()  asm volatile("cp.async.commit_group;" ::: "memory")
#define CP_WAIT0()   asm volatile("cp.async.wait_group 0;" ::: "memory")

// ---------------------------------------------------------------------------
// 1) upflow: transposed conv, stride 2, 4x4 kernel, groups=2
// ---------------------------------------------------------------------------
__global__ void k_upflow(const float* __restrict__ flow, const float* __restrict__ wu)
{
    int idx = blockIdx.x * blockDim.x + threadIdx.x;
    if (idx >= BB*2*HW) return;
    int ox = idx & 127;
    int oy = (idx >> 7) & 127;
    int c  = (idx >> 14) & 1;
    int b  = idx >> 15;
    const float* f  = flow + (b*2 + c) * 64 * 64;
    const float* wc = wu + c * 16;
    int py = oy & 1, px = ox & 1;
    float s = 0.f;
#pragma unroll
    for (int i = 0; i < 2; i++) {
        int ky  = py + 2*i;
        int jy2 = oy + ky - 2;
        if (jy2 < 0 || jy2 > 126) continue;
        int jy = jy2 >> 1;
#pragma unroll
        for (int j = 0; j < 2; j++) {
            int kx  = px + 2*j;
            int jx2 = ox + kx - 2;
            if (jx2 < 0 || jx2 > 126) continue;
            int jx = jx2 >> 1;
            s += f[jy*64 + jx] * wc[(3-ky)*4 + (3-kx)];
        }
    }
    g_flow[idx] = s;
}

// ---------------------------------------------------------------------------
// 2) backward warp of featSecond by 2.5*flow, bilinear zero-border + mask
// ---------------------------------------------------------------------------
__global__ void k_warp(const float* __restrict__ feat)
{
    int idx = blockIdx.x * blockDim.x + threadIdx.x;
    if (idx >= BB*HW) return;
    int x = idx & 127;
    int y = (idx >> 7) & 127;
    int b = idx >> 14;

    float fx = (float)x + 2.5f * g_flow[(b*2 + 0)*HW + y*WW + x];
    float fy = (float)y + 2.5f * g_flow[(b*2 + 1)*HW + y*WW + x];

    float x0f = floorf(fx), y0f = floorf(fy);
    float x1f = x0f + 1.f,  y1f = y0f + 1.f;
    float wa = (x1f - fx) * (y1f - fy);
    float wb = (fx - x0f) * (y1f - fy);
    float wc = (x1f - fx) * (fy - y0f);
    float wd = (fx - x0f) * (fy - y0f);

    int x0 = (int)x0f, y0 = (int)y0f, x1 = x0 + 1, y1 = y0 + 1;
    float vx0 = (x0 >= 0 && x0 < WW) ? 1.f : 0.f;
    float vx1 = (x1 >= 0 && x1 < WW) ? 1.f : 0.f;
    float vy0 = (y0 >= 0 && y0 < HH) ? 1.f : 0.f;
    float vy1 = (y1 >= 0 && y1 < HH) ? 1.f : 0.f;
    float va = vx0*vy0, vb = vx1*vy0, vc = vx0*vy1, vd = vx1*vy1;

    float onew = wa*va + wb*vb + wc*vc + wd*vd;
    float mask = (onew > 0.999f) ? 1.f : 0.f;

    float ka = wa*va*mask, kb = wb*vb*mask, kc = wc*vc*mask, kd = wd*vd*mask;

    int cx0 = min(max(x0, 0), WW-1), cx1 = min(max(x1, 0), WW-1);
    int cy0 = min(max(y0, 0), HH-1), cy1 = min(max(y1, 0), HH-1);
    int ia = cy0*WW + cx0, ib2 = cy0*WW + cx1, ic2 = cy1*WW + cx0, id2 = cy1*WW + cx1;

    const float* base = feat + (size_t)b*CF*HW;
    float* out = g_feat2 + (size_t)b*CF*HW + y*WW + x;
#pragma unroll 4
    for (int c = 0; c < CF; c++) {
        const float* p = base + c*HW;
        out[c*HW] = ka*__ldg(p+ia) + kb*__ldg(p+ib2) + kc*__ldg(p+ic2) + kd*__ldg(p+id2);
    }
}

// ---------------------------------------------------------------------------
// 3) correlation (7x7 displacements, mean over 96 channels) + leaky relu
// ---------------------------------------------------------------------------
__global__ __launch_bounds__(256) void k_corr(const float* __restrict__ f1)
{
    __shared__ float s2[22*22];
    int tx = threadIdx.x, ty = threadIdx.y;
    int tid = ty*16 + tx;
    int bx0 = blockIdx.x * 16, by0 = blockIdx.y * 16;
    int b = blockIdx.z;
    int x = bx0 + tx, y = by0 + ty;
    int ox0 = bx0 - 3, oy0 = by0 - 3;

    float acc[49];
#pragma unroll
    for (int d = 0; d < 49; d++) acc[d] = 0.f;

    const float* F1 = f1 + (size_t)b*CF*HW;
    const float* F2 = g_feat2 + (size_t)b*CF*HW;

    for (int c = 0; c < CF; c++) {
        __syncthreads();
#pragma unroll
        for (int i = tid; i < 22*22; i += 256) {
            int ly = i / 22, lx = i - ly*22;
            int gy = oy0 + ly, gx = ox0 + lx;
            float v = 0.f;
            if (gy >= 0 && gy < HH && gx >= 0 && gx < WW)
                v = F2[c*HW + gy*WW + gx];
            s2[i] = v;
        }
        float a1 = F1[c*HW + y*WW + x];
        __syncthreads();
#pragma unroll
        for (int dy = 0; dy < 7; dy++)
#pragma unroll
            for (int dx = 0; dx < 7; dx++)
                acc[dy*7 + dx] += a1 * s2[(ty+dy)*22 + tx + dx];
    }

    const float inv = 1.f / 96.f;
    float* out = g_corr + (size_t)b*49*HW + y*WW + x;
#pragma unroll
    for (int d = 0; d < 49; d++) {
        float v = acc[d] * inv;
        out[d*HW] = (v >= 0.f) ? v : 0.1f * v;
    }
}

// ---------------------------------------------------------------------------
// 4) 3x3 conv, pad 1, f32x2-packed, double-buffered cp.async staging.
//    Each thread: 2(x) x 4(y) pixels, OCT output channels.
//    Block 16x16 -> spatial tile 32(w) x 64(h). One barrier per input channel.
// ---------------------------------------------------------------------------
template <int IC, int OC, int OCT>
__global__ __launch_bounds__(256, 2) void k_conv3db(const float* __restrict__ in,
                                                    const float* __restrict__ w,
                                                    const float* __restrict__ bias,
                                                    float* __restrict__ out)
{
    __shared__ __align__(16) float s_in[2][66*34];
    __shared__ __align__(16) float s_w2[2][OCT*9*2];  // duplicated (w,w) pairs
    int tx = threadIdx.x, ty = threadIdx.y;
    int tid = ty*16 + tx;
    int tile = blockIdx.x;            // 0..7 : 4 x-tiles * 2 y-tiles
    int tbx = (tile & 3) * 32;
    int tby = (tile >> 2) * 64;
    int ocb = blockIdx.y * OCT;
    int b = blockIdx.z;

    unsigned long long acc[OCT][4];
#pragma unroll
    for (int o = 0; o < OCT; o++) {
        float bb = bias[ocb + o];
        unsigned long long bp = pack2(bb, bb);
#pragma unroll
        for (int py = 0; py < 4; py++) acc[o][py] = bp;
    }

    const float* IN = in + (size_t)b*IC*HW;
    const uint32_t s_in_base[2]  = { smem_u32(&s_in[0][0]),  smem_u32(&s_in[1][0]) };
    const uint32_t s_w2_base[2]  = { smem_u32(&s_w2[0][0]),  smem_u32(&s_w2[1][0]) };

    // async stagers -------------------------------------------------------
    auto stage_in = [&](int ic, int buf) {
        const float* src = IN + ic*HW;
        uint32_t sb = s_in_base[buf];
#pragma unroll
        for (int i = tid; i < 66*34; i += 256) {
            int ly = i / 34, lx = i - ly*34;
            int gy = tby - 1 + ly, gx = tbx - 1 + lx;
            if (gy >= 0 && gy < HH && gx >= 0 && gx < WW)
                cp4(sb + i*4, src + gy*WW + gx);
            else
                s_in[buf][i] = 0.f;           // zero-pad via plain STS
        }
    };
    auto stage_w = [&](int ic, int buf) {
        // duplicate each weight via two 4B async copies of the same source
        if (tid < OCT*9*2) {
            int e = tid >> 1;                 // weight element 0..OCT*9-1
            int o = e / 9, t = e - o*9;
            cp4(s_w2_base[buf] + tid*4, w + ((size_t)(ocb + o)*IC + ic)*9 + t);
        }
    };

    // prologue: prefetch channel 0 into buffer 0
    stage_in(0, 0);
    stage_w(0, 0);
    CP_COMMIT();

    for (int ic = 0; ic < IC; ic++) {
        int cur = ic & 1;
        CP_WAIT0();          // channel ic's copies (this thread) complete
        __syncthreads();     // all threads' copies visible; prev compute done

        if (ic + 1 < IC) {   // prefetch ic+1 into the other buffer
            stage_in(ic + 1, cur ^ 1);
            stage_w(ic + 1, cur ^ 1);
            CP_COMMIT();
        }

        const float* sin = &s_in[cur][0];
        const float* sw  = &s_w2[cur][0];
#pragma unroll
        for (int r = 0; r < 3; r++) {
            unsigned long long p0[4], p1[4], p2[4];
#pragma unroll
            for (int py = 0; py < 4; py++) {
                const float* rp = &sin[(ty*4 + r + py)*34 + 2*tx];
                p0[py] = *(const unsigned long long*)(rp);       // cols (s=0, s=1)
                p2[py] = *(const unsigned long long*)(rp + 2);   // cols (s=2, s=3)
                unsigned int mlo = (unsigned int)(p0[py] >> 32);
                unsigned int mhi = (unsigned int)(p2[py]);
                p1[py] = ((unsigned long long)mhi << 32) | mlo;  // cols (s=1, s=2)
            }
#pragma unroll
            for (int o = 0; o < OCT; o++) {
                unsigned long long w0 = *(const unsigned long long*)&sw[(o*9 + r*3 + 0)*2];
                unsigned long long w1 = *(const unsigned long long*)&sw[(o*9 + r*3 + 1)*2];
                unsigned long long w2v= *(const unsigned long long*)&sw[(o*9 + r*3 + 2)*2];
#pragma unroll
                for (int py = 0; py < 4; py++) {
                    FMA2(acc[o][py], p0[py], w0,  acc[o][py]);
                    FMA2(acc[o][py], p1[py], w1,  acc[o][py]);
                    FMA2(acc[o][py], p2[py], w2v, acc[o][py]);
                }
            }
        }
    }

    int x0 = tbx + 2*tx;
#pragma unroll
    for (int o = 0; o < OCT; o++) {
#pragma unroll
        for (int py = 0; py < 4; py++) {
            int y = tby + ty*4 + py;
            float a0 = __uint_as_float((unsigned int)(acc[o][py] & 0xFFFFFFFFull));
            float a1 = __uint_as_float((unsigned int)(acc[o][py] >> 32));
            a0 = (a0 >= 0.f) ? a0 : 0.1f*a0;
            a1 = (a1 >= 0.f) ? a1 : 0.1f*a1;
            *(float2*)&out[((size_t)b*OC + ocb + o)*HW + y*WW + x0] = make_float2(a0, a1);
        }
    }
}

// ---------------------------------------------------------------------------
// 5) final 5x5 conv (32 -> 2, pad 2), add upsampled flow, write d_out
// ---------------------------------------------------------------------------
__global__ __launch_bounds__(256) void k_conv5(const float* __restrict__ w,
                                               const float* __restrict__ bias,
                                               float* __restrict__ out)
{
    __shared__ float s_in[20*20];
    __shared__ float s_w[2*25];
    int tx = threadIdx.x, ty = threadIdx.y;
    int tid = ty*16 + tx;
    int tile = blockIdx.x;
    int tbx = (tile & 7) * 16, tby = (tile >> 3) * 16;
    int b = blockIdx.z;
    int x = tbx + tx, y = tby + ty;

    float acc0 = bias[0], acc1 = bias[1];
    const float* IN = g_x3 + (size_t)b*32*HW;

    for (int ic = 0; ic < 32; ic++) {
        __syncthreads();
#pragma unroll
        for (int i = tid; i < 400; i += 256) {
            int ly = i / 20, lx = i - ly*20;
            int gy = tby - 2 + ly, gx = tbx - 2 + lx;
            float v = 0.f;
            if (gy >= 0 && gy < HH && gx >= 0 && gx < WW)
                v = IN[ic*HW + gy*WW + gx];
            s_in[i] = v;
        }
        if (tid < 50) {
            int o = tid / 25, t = tid - o*25;
            s_w[tid] = w[((size_t)o*32 + ic)*25 + t];
        }
        __syncthreads();

#pragma unroll
        for (int t = 0; t < 25; t++) {
            int r = t / 5, s = t - r*5;
            float iv = s_in[(ty + r)*20 + tx + s];
            acc0 += iv * s_w[t];
            acc1 += iv * s_w[25 + t];
        }
    }

    int pix = y*WW + x;
    out[((size_t)b*2 + 0)*HW + pix] = g_flow[(b*2 + 0)*HW + pix] + acc0;
    out[((size_t)b*2 + 1)*HW + pix] = g_flow[(b*2 + 1)*HW + pix] + acc1;
}

// ---------------------------------------------------------------------------
extern "C" void kernel_launch(void* const* d_in, const int* in_sizes, int n_in,
                              void* d_out, int out_size)
{
    const float* featFirst  = (const float*)d_in[2];
    const float* featSecond = (const float*)d_in[3];
    const float* tflow      = (const float*)d_in[4];
    const float* wu         = (const float*)d_in[5];
    const float* w1 = (const float*)d_in[6];
    const float* b1 = (const float*)d_in[7];
    const float* w2 = (const float*)d_in[8];
    const float* b2 = (const float*)d_in[9];
    const float* w3 = (const float*)d_in[10];
    const float* b3 = (const float*)d_in[11];
    const float* w4 = (const float*)d_in[12];
    const float* b4 = (const float*)d_in[13];

    float *corrp, *x1p, *x2p, *x3p;
    cudaGetSymbolAddress((void**)&corrp, g_corr);
    cudaGetSymbolAddress((void**)&x1p, g_x1);
    cudaGetSymbolAddress((void**)&x2p, g_x2);
    cudaGetSymbolAddress((void**)&x3p, g_x3);

    dim3 blk(16, 16);

    k_upflow<<<(BB*2*HW + 255)/256, 256>>>(tflow, wu);
    k_warp<<<(BB*HW + 255)/256, 256>>>(featSecond);
    k_corr<<<dim3(8, 8, BB), blk>>>(featFirst);
    k_conv3db<49, 128, 8><<<dim3(8, 16, BB), blk>>>(corrp, w1, b1, x1p);
    k_conv3db<128, 64, 8><<<dim3(8,  8, BB), blk>>>(x1p,  w2, b2, x2p);
    k_conv3db<64,  32, 8><<<dim3(8,  4, BB), blk>>>(x2p,  w3, b3, x3p);
    k_conv5<<<dim3(64, 1, BB), blk>>>(w4, b4, (float*)d_out);
}

// round 12
// speedup vs baseline: 1.8334x; 1.2402x over previous
#include <cuda_runtime.h>
#include <math.h>
#include <stdint.h>

// Problem constants
#define BB 16
#define CF 96
#define HH 128
#define WW 128
#define HW (HH*WW)

// Scratch (static device allocations are allowed)
__device__ float g_flow[BB*2*HW];        //   2 MB
__device__ float g_feat2[BB*CF*HW];      //  96 MB
__device__ float g_corr[BB*49*HW];       //  49 MB
__device__ float g_x1[BB*128*HW];        // 128 MB
__device__ float g_x2[BB*64*HW];         //  64 MB
__device__ float g_x3[BB*32*HW];         //  32 MB

// Packed f32x2 FMA (FFMA2 in SASS; PTX-only form)
#define FMA2(d,a,b,c) asm("fma.rn.f32x2 %0, %1, %2, %3;" : "=l"(d) : "l"(a), "l"(b), "l"(c))

__device__ __forceinline__ unsigned long long pack2(float lo, float hi) {
    unsigned long long r;
    asm("mov.b64 %0, {%1, %2};" : "=l"(r) : "f"(lo), "f"(hi));
    return r;
}

__device__ __forceinline__ uint32_t smem_u32(const void* p) {
    return (uint32_t)__cvta_generic_to_shared(p);
}
__device__ __forceinline__ void cp4(uint32_t dst, const void* src) {
    asm volatile("cp.async.ca.shared.global [%0], [%1], 4;" :: "r"(dst), "l"(src));
}
#define CP_COMMIT()  asm volatile("cp.async.commit_group;" ::: "memory")
#define CP_WAIT0()   asm volatile("cp.async.wait_group 0;" ::: "memory")

// ---------------------------------------------------------------------------
// 1) upflow: transposed conv, stride 2, 4x4 kernel, groups=2
// ---------------------------------------------------------------------------
__global__ void k_upflow(const float* __restrict__ flow, const float* __restrict__ wu)
{
    int idx = blockIdx.x * blockDim.x + threadIdx.x;
    if (idx >= BB*2*HW) return;
    int ox = idx & 127;
    int oy = (idx >> 7) & 127;
    int c  = (idx >> 14) & 1;
    int b  = idx >> 15;
    const float* f  = flow + (b*2 + c) * 64 * 64;
    const float* wc = wu + c * 16;
    int py = oy & 1, px = ox & 1;
    float s = 0.f;
#pragma unroll
    for (int i = 0; i < 2; i++) {
        int ky  = py + 2*i;
        int jy2 = oy + ky - 2;
        if (jy2 < 0 || jy2 > 126) continue;
        int jy = jy2 >> 1;
#pragma unroll
        for (int j = 0; j < 2; j++) {
            int kx  = px + 2*j;
            int jx2 = ox + kx - 2;
            if (jx2 < 0 || jx2 > 126) continue;
            int jx = jx2 >> 1;
            s += f[jy*64 + jx] * wc[(3-ky)*4 + (3-kx)];
        }
    }
    g_flow[idx] = s;
}

// ---------------------------------------------------------------------------
// 2) backward warp of featSecond by 2.5*flow, bilinear zero-border + mask
// ---------------------------------------------------------------------------
__global__ void k_warp(const float* __restrict__ feat)
{
    int idx = blockIdx.x * blockDim.x + threadIdx.x;
    if (idx >= BB*HW) return;
    int x = idx & 127;
    int y = (idx >> 7) & 127;
    int b = idx >> 14;

    float fx = (float)x + 2.5f * g_flow[(b*2 + 0)*HW + y*WW + x];
    float fy = (float)y + 2.5f * g_flow[(b*2 + 1)*HW + y*WW + x];

    float x0f = floorf(fx), y0f = floorf(fy);
    float x1f = x0f + 1.f,  y1f = y0f + 1.f;
    float wa = (x1f - fx) * (y1f - fy);
    float wb = (fx - x0f) * (y1f - fy);
    float wc = (x1f - fx) * (fy - y0f);
    float wd = (fx - x0f) * (fy - y0f);

    int x0 = (int)x0f, y0 = (int)y0f, x1 = x0 + 1, y1 = y0 + 1;
    float vx0 = (x0 >= 0 && x0 < WW) ? 1.f : 0.f;
    float vx1 = (x1 >= 0 && x1 < WW) ? 1.f : 0.f;
    float vy0 = (y0 >= 0 && y0 < HH) ? 1.f : 0.f;
    float vy1 = (y1 >= 0 && y1 < HH) ? 1.f : 0.f;
    float va = vx0*vy0, vb = vx1*vy0, vc = vx0*vy1, vd = vx1*vy1;

    float onew = wa*va + wb*vb + wc*vc + wd*vd;
    float mask = (onew > 0.999f) ? 1.f : 0.f;

    float ka = wa*va*mask, kb = wb*vb*mask, kc = wc*vc*mask, kd = wd*vd*mask;

    int cx0 = min(max(x0, 0), WW-1), cx1 = min(max(x1, 0), WW-1);
    int cy0 = min(max(y0, 0), HH-1), cy1 = min(max(y1, 0), HH-1);
    int ia = cy0*WW + cx0, ib2 = cy0*WW + cx1, ic2 = cy1*WW + cx0, id2 = cy1*WW + cx1;

    const float* base = feat + (size_t)b*CF*HW;
    float* out = g_feat2 + (size_t)b*CF*HW + y*WW + x;
#pragma unroll 4
    for (int c = 0; c < CF; c++) {
        const float* p = base + c*HW;
        out[c*HW] = ka*__ldg(p+ia) + kb*__ldg(p+ib2) + kc*__ldg(p+ic2) + kd*__ldg(p+id2);
    }
}

// ---------------------------------------------------------------------------
// 3) correlation (7x7 displacements, mean over 96 channels) + leaky relu
// ---------------------------------------------------------------------------
__global__ __launch_bounds__(256) void k_corr(const float* __restrict__ f1)
{
    __shared__ float s2[22*22];
    int tx = threadIdx.x, ty = threadIdx.y;
    int tid = ty*16 + tx;
    int bx0 = blockIdx.x * 16, by0 = blockIdx.y * 16;
    int b = blockIdx.z;
    int x = bx0 + tx, y = by0 + ty;
    int ox0 = bx0 - 3, oy0 = by0 - 3;

    float acc[49];
#pragma unroll
    for (int d = 0; d < 49; d++) acc[d] = 0.f;

    const float* F1 = f1 + (size_t)b*CF*HW;
    const float* F2 = g_feat2 + (size_t)b*CF*HW;

    for (int c = 0; c < CF; c++) {
        __syncthreads();
#pragma unroll
        for (int i = tid; i < 22*22; i += 256) {
            int ly = i / 22, lx = i - ly*22;
            int gy = oy0 + ly, gx = ox0 + lx;
            float v = 0.f;
            if (gy >= 0 && gy < HH && gx >= 0 && gx < WW)
                v = F2[c*HW + gy*WW + gx];
            s2[i] = v;
        }
        float a1 = F1[c*HW + y*WW + x];
        __syncthreads();
#pragma unroll
        for (int dy = 0; dy < 7; dy++)
#pragma unroll
            for (int dx = 0; dx < 7; dx++)
                acc[dy*7 + dx] += a1 * s2[(ty+dy)*22 + tx + dx];
    }

    const float inv = 1.f / 96.f;
    float* out = g_corr + (size_t)b*49*HW + y*WW + x;
#pragma unroll
    for (int d = 0; d < 49; d++) {
        float v = acc[d] * inv;
        out[d*HW] = (v >= 0.f) ? v : 0.1f * v;
    }
}

// ---------------------------------------------------------------------------
// 4) 3x3 conv, pad 1, f32x2-packed, double-buffered cp.async staging,
//    2 input channels per barrier round, hoisted loop-invariant addressing.
//    Each thread: 2(x) x 4(y) pixels, OCT output channels.
//    Block 16x16 -> spatial tile 32(w) x 64(h).
// ---------------------------------------------------------------------------
template <int IC, int OC, int OCT>
__global__ __launch_bounds__(256, 2) void k_conv3p(const float* __restrict__ in,
                                                   const float* __restrict__ w,
                                                   const float* __restrict__ bias,
                                                   float* __restrict__ out)
{
    constexpr int TILE = 66*34;
    __shared__ __align__(16) float s_in[2][2][TILE];        // [buf][chan]
    __shared__ __align__(16) float s_w2[2][2][OCT*9*2];     // duplicated (w,w)
    int tx = threadIdx.x, ty = threadIdx.y;
    int tid = ty*16 + tx;
    int tile = blockIdx.x;            // 0..7 : 4 x-tiles * 2 y-tiles
    int tbx = (tile & 3) * 32;
    int tby = (tile >> 2) * 64;
    int ocb = blockIdx.y * OCT;
    int b = blockIdx.z;

    unsigned long long acc[OCT][4];
#pragma unroll
    for (int o = 0; o < OCT; o++) {
        float bb = bias[ocb + o];
        unsigned long long bp = pack2(bb, bb);
#pragma unroll
        for (int py = 0; py < 4; py++) acc[o][py] = bp;
    }

    const float* IN = in + (size_t)b*IC*HW;

    // pre-zero both input buffers (halo positions stay zero forever)
    for (int i = tid; i < 2*2*TILE; i += 256) ((float*)s_in)[i] = 0.f;

    // hoisted per-thread staging map: 9 slots cover TILE=2244 elements
    uint32_t soff[9];
    const float* gsrc[9];
    bool val[9];
#pragma unroll
    for (int k = 0; k < 9; k++) {
        int i = tid + k*256;
        int ly = i / 34, lx = i - ly*34;
        int gy = tby - 1 + ly, gx = tbx - 1 + lx;
        val[k] = (i < TILE) && gy >= 0 && gy < HH && gx >= 0 && gx < WW;
        soff[k] = (uint32_t)i * 4u;
        gsrc[k] = IN + gy*WW + gx;
    }
    // hoisted weight source for this thread (2 threads per weight element)
    const float* wsrc = w;
    bool wact = tid < OCT*9*2;
    if (wact) {
        int e = tid >> 1;
        int o = e / 9, t = e - o*9;
        wsrc = w + ((size_t)(ocb + o)*IC)*9 + t;
    }

    uint32_t sin_base[2][2], sw_base[2][2];
#pragma unroll
    for (int bf = 0; bf < 2; bf++)
#pragma unroll
        for (int ch = 0; ch < 2; ch++) {
            sin_base[bf][ch] = smem_u32(&s_in[bf][ch][0]);
            sw_base[bf][ch]  = smem_u32(&s_w2[bf][ch][0]);
        }

    auto stage_pair = [&](int c0, int bf) {
#pragma unroll
        for (int k = 0; k < 9; k++)
            if (val[k]) cp4(sin_base[bf][0] + soff[k], gsrc[k] + (size_t)c0*HW);
        if (c0 + 1 < IC) {
#pragma unroll
            for (int k = 0; k < 9; k++)
                if (val[k]) cp4(sin_base[bf][1] + soff[k], gsrc[k] + (size_t)(c0+1)*HW);
        }
        if (wact) {
            cp4(sw_base[bf][0] + tid*4, wsrc + c0*9);
            if (c0 + 1 < IC) cp4(sw_base[bf][1] + tid*4, wsrc + (c0+1)*9);
        }
    };

    auto compute = [&](const float* sin, const float* sw) {
#pragma unroll
        for (int r = 0; r < 3; r++) {
            unsigned long long p0[4], p1[4], p2[4];
#pragma unroll
            for (int py = 0; py < 4; py++) {
                const float* rp = &sin[(ty*4 + r + py)*34 + 2*tx];
                p0[py] = *(const unsigned long long*)(rp);       // cols (s=0, s=1)
                p2[py] = *(const unsigned long long*)(rp + 2);   // cols (s=2, s=3)
                unsigned int lo0, hi0, lo2, hi2;
                asm("mov.b64 {%0,%1}, %2;" : "=r"(lo0), "=r"(hi0) : "l"(p0[py]));
                asm("mov.b64 {%0,%1}, %2;" : "=r"(lo2), "=r"(hi2) : "l"(p2[py]));
                asm("mov.b64 %0, {%1,%2};" : "=l"(p1[py]) : "r"(hi0), "r"(lo2));
            }
#pragma unroll
            for (int o = 0; o < OCT; o++) {
                unsigned long long w0 = *(const unsigned long long*)&sw[(o*9 + r*3 + 0)*2];
                unsigned long long w1 = *(const unsigned long long*)&sw[(o*9 + r*3 + 1)*2];
                unsigned long long w2v= *(const unsigned long long*)&sw[(o*9 + r*3 + 2)*2];
#pragma unroll
                for (int py = 0; py < 4; py++) {
                    FMA2(acc[o][py], p0[py], w0,  acc[o][py]);
                    FMA2(acc[o][py], p1[py], w1,  acc[o][py]);
                    FMA2(acc[o][py], p2[py], w2v, acc[o][py]);
                }
            }
        }
    };

    __syncthreads();                 // zeros visible before first compute
    stage_pair(0, 0);
    CP_COMMIT();

    for (int c0 = 0; c0 < IC; c0 += 2) {
        int bf = (c0 >> 1) & 1;
        CP_WAIT0();
        __syncthreads();
        if (c0 + 2 < IC) {
            stage_pair(c0 + 2, bf ^ 1);
            CP_COMMIT();
        }
        compute(&s_in[bf][0][0], &s_w2[bf][0][0]);
        if (c0 + 1 < IC) compute(&s_in[bf][1][0], &s_w2[bf][1][0]);
    }

    int x0 = tbx + 2*tx;
#pragma unroll
    for (int o = 0; o < OCT; o++) {
#pragma unroll
        for (int py = 0; py < 4; py++) {
            int y = tby + ty*4 + py;
            float a0 = __uint_as_float((unsigned int)(acc[o][py] & 0xFFFFFFFFull));
            float a1 = __uint_as_float((unsigned int)(acc[o][py] >> 32));
            a0 = (a0 >= 0.f) ? a0 : 0.1f*a0;
            a1 = (a1 >= 0.f) ? a1 : 0.1f*a1;
            *(float2*)&out[((size_t)b*OC + ocb + o)*HW + y*WW + x0] = make_float2(a0, a1);
        }
    }
}

// ---------------------------------------------------------------------------
// 5) final 5x5 conv (32 -> 2, pad 2), add upsampled flow, write d_out
// ---------------------------------------------------------------------------
__global__ __launch_bounds__(256) void k_conv5(const float* __restrict__ w,
                                               const float* __restrict__ bias,
                                               float* __restrict__ out)
{
    __shared__ float s_in[20*20];
    __shared__ float s_w[2*25];
    int tx = threadIdx.x, ty = threadIdx.y;
    int tid = ty*16 + tx;
    int tile = blockIdx.x;
    int tbx = (tile & 7) * 16, tby = (tile >> 3) * 16;
    int b = blockIdx.z;
    int x = tbx + tx, y = tby + ty;

    float acc0 = bias[0], acc1 = bias[1];
    const float* IN = g_x3 + (size_t)b*32*HW;

    for (int ic = 0; ic < 32; ic++) {
        __syncthreads();
#pragma unroll
        for (int i = tid; i < 400; i += 256) {
            int ly = i / 20, lx = i - ly*20;
            int gy = tby - 2 + ly, gx = tbx - 2 + lx;
            float v = 0.f;
            if (gy >= 0 && gy < HH && gx >= 0 && gx < WW)
                v = IN[ic*HW + gy*WW + gx];
            s_in[i] = v;
        }
        if (tid < 50) {
            int o = tid / 25, t = tid - o*25;
            s_w[tid] = w[((size_t)o*32 + ic)*25 + t];
        }
        __syncthreads();

#pragma unroll
        for (int t = 0; t < 25; t++) {
            int r = t / 5, s = t - r*5;
            float iv = s_in[(ty + r)*20 + tx + s];
            acc0 += iv * s_w[t];
            acc1 += iv * s_w[25 + t];
        }
    }

    int pix = y*WW + x;
    out[((size_t)b*2 + 0)*HW + pix] = g_flow[(b*2 + 0)*HW + pix] + acc0;
    out[((size_t)b*2 + 1)*HW + pix] = g_flow[(b*2 + 1)*HW + pix] + acc1;
}

// ---------------------------------------------------------------------------
extern "C" void kernel_launch(void* const* d_in, const int* in_sizes, int n_in,
                              void* d_out, int out_size)
{
    const float* featFirst  = (const float*)d_in[2];
    const float* featSecond = (const float*)d_in[3];
    const float* tflow      = (const float*)d_in[4];
    const float* wu         = (const float*)d_in[5];
    const float* w1 = (const float*)d_in[6];
    const float* b1 = (const float*)d_in[7];
    const float* w2 = (const float*)d_in[8];
    const float* b2 = (const float*)d_in[9];
    const float* w3 = (const float*)d_in[10];
    const float* b3 = (const float*)d_in[11];
    const float* w4 = (const float*)d_in[12];
    const float* b4 = (const float*)d_in[13];

    float *corrp, *x1p, *x2p, *x3p;
    cudaGetSymbolAddress((void**)&corrp, g_corr);
    cudaGetSymbolAddress((void**)&x1p, g_x1);
    cudaGetSymbolAddress((void**)&x2p, g_x2);
    cudaGetSymbolAddress((void**)&x3p, g_x3);

    dim3 blk(16, 16);

    k_upflow<<<(BB*2*HW + 255)/256, 256>>>(tflow, wu);
    k_warp<<<(BB*HW + 255)/256, 256>>>(featSecond);
    k_corr<<<dim3(8, 8, BB), blk>>>(featFirst);
    k_conv3p<49, 128, 8><<<dim3(8, 16, BB), blk>>>(corrp, w1, b1, x1p);
    k_conv3p<128, 64, 8><<<dim3(8,  8, BB), blk>>>(x1p,  w2, b2, x2p);
    k_conv3p<64,  32, 8><<<dim3(8,  4, BB), blk>>>(x2p,  w3, b3, x3p);
    k_conv5<<<dim3(64, 1, BB), blk>>>(w4, b4, (float*)d_out);
}